// round 11
// baseline (speedup 1.0000x reference)
#include <cstdint>
#include <cuda.h>
#include <cuda_runtime.h>
#include <cuda_fp16.h>
#include <cuda_bf16.h>
#include <mma.h>

using namespace nvcuda;

// Problem constants
#define B_     4
#define T_     1024
#define HW_    1296
#define NBINS_ 512
#define LOOKUP_ 101
#define PAD_   50
#define ODIM_  128
#define TT_    32              // centers per block
#define JT_    144             // neighbor rows per block
#define KCH_   64              // k-chunk halfs (128B row)
#define SIMS_LD 136
#define WIN_K  112             // epilogue K padded to 7 x 16
#define W_LDH  136             // Wsm row stride (halfs), 16B-multiple
#define NGROUPS_ 4
#define GTHREADS_ 192          // 6 warps per group
#define NTHREADS_ 768
#define WPF_   17              // fc_w prefetch regs: 102*128/768 = 17 exactly

#define BUF_HALFS (JT_ * KCH_)                 // 9216 halfs = 18432 B
#define TMA_BYTES (BUF_HALFS * 2)
#define YS_BYTES  (NGROUPS_ * 2 * TMA_BYTES)   // 147456 B
#define YS_FLOATS (YS_BYTES / 4)
#define SIMS_TOT  (NGROUPS_ * TT_ * SIMS_LD)   // 17408 floats (4 buffers)
#define SMEM_BYTES (YS_BYTES + SIMS_TOT * 4 + 64)

// Scratch: normalized histograms in fp16, (B*T, 512) = 4 MB
__device__ __half g_hist_h[B_ * T_ * NBINS_];

// ---------------------------------------------------------------------------
// Kernel 1: per-frame histogram + L2 normalize -> fp16. HBM-bound (at floor).
// ---------------------------------------------------------------------------
__global__ __launch_bounds__(256) void hist_kernel(const int* __restrict__ frames)
{
    __shared__ unsigned int h[NBINS_];
    __shared__ float red[8];

    const int bt = blockIdx.x;
    const int tid = threadIdx.x;
    const int* f = frames + (size_t)bt * HW_ * 3;

    #pragma unroll
    for (int i = tid; i < NBINS_; i += 256) h[i] = 0u;
    __syncthreads();

    for (int grp = tid; grp < HW_ / 4; grp += 256) {
        const int4* p4 = (const int4*)(f + grp * 12);
        int4 v0 = p4[0];
        int4 v1 = p4[1];
        int4 v2 = p4[2];
        int b0 = ((v0.x >> 5) << 6) | ((v0.y >> 5) << 3) | (v0.z >> 5);
        int b1 = ((v0.w >> 5) << 6) | ((v1.x >> 5) << 3) | (v1.y >> 5);
        int b2 = ((v1.z >> 5) << 6) | ((v1.w >> 5) << 3) | (v2.x >> 5);
        int b3 = ((v2.y >> 5) << 6) | ((v2.z >> 5) << 3) | (v2.w >> 5);
        atomicAdd(&h[b0], 1u);
        atomicAdd(&h[b1], 1u);
        atomicAdd(&h[b2], 1u);
        atomicAdd(&h[b3], 1u);
    }
    __syncthreads();

    float s = 0.f;
    #pragma unroll
    for (int i = tid; i < NBINS_; i += 256) {
        float v = (float)h[i];
        s += v * v;
    }
    #pragma unroll
    for (int o = 16; o; o >>= 1) s += __shfl_down_sync(0xffffffffu, s, o);
    if ((tid & 31) == 0) red[tid >> 5] = s;
    __syncthreads();
    if (tid == 0) {
        float t = 0.f;
        #pragma unroll
        for (int i = 0; i < 8; i++) t += red[i];
        red[0] = 1.0f / fmaxf(sqrtf(t), 1e-12f);
    }
    __syncthreads();
    const float inv = red[0];

    __half* dst = g_hist_h + (size_t)bt * NBINS_;
    #pragma unroll
    for (int i = tid; i < NBINS_; i += 256)
        dst[i] = __float2half_rn((float)h[i] * inv);
}

// ---------------------------------------------------------------------------
__device__ __forceinline__ void mbar_wait(unsigned int addr, int phase)
{
    asm volatile(
        "{\n\t"
        ".reg .pred P;\n\t"
        "W%=:\n\t"
        "mbarrier.try_wait.parity.shared.b64 P, [%0], %1;\n\t"
        "@P bra D%=;\n\t"
        "bra W%=;\n\t"
        "D%=:\n\t"
        "}"
        :: "r"(addr), "r"(phase) : "memory");
}

__device__ __forceinline__ void ldsm_x4(unsigned int addr,
                                        unsigned& r0, unsigned& r1,
                                        unsigned& r2, unsigned& r3)
{
    asm volatile("ldmatrix.sync.aligned.m8n8.x4.shared.b16 {%0,%1,%2,%3}, [%4];"
                 : "=r"(r0), "=r"(r1), "=r"(r2), "=r"(r3) : "r"(addr));
}

__device__ __forceinline__ void ldsm_x2(unsigned int addr,
                                        unsigned& r0, unsigned& r1)
{
    asm volatile("ldmatrix.sync.aligned.m8n8.x2.shared.b16 {%0,%1}, [%2];"
                 : "=r"(r0), "=r"(r1) : "r"(addr));
}

__device__ __forceinline__ void mma_f16(float (&d)[4],
                                        unsigned a0, unsigned a1, unsigned a2, unsigned a3,
                                        unsigned b0, unsigned b1)
{
    asm volatile(
        "mma.sync.aligned.m16n8k16.row.col.f32.f16.f16.f32 "
        "{%0,%1,%2,%3},{%4,%5,%6,%7},{%8,%9},{%0,%1,%2,%3};"
        : "+f"(d[0]), "+f"(d[1]), "+f"(d[2]), "+f"(d[3])
        : "r"(a0), "r"(a1), "r"(a2), "r"(a3), "r"(b0), "r"(b1));
}

// ---------------------------------------------------------------------------
// Kernel 2: banded similarity (fp16 ldmatrix + m16n8k16 mma, 4-way k-split,
//           single-wait TMA) + fp16 wmma FC epilogue
// ---------------------------------------------------------------------------
__global__ __launch_bounds__(NTHREADS_, 1) void band_fc_v8(
    const __grid_constant__ CUtensorMap tmap,
    const float* __restrict__ fc_w,   // (101,128)
    const float* __restrict__ fc_b,   // (128,)
    float* __restrict__ out)          // (B,T,128)
{
    extern __shared__ __align__(1024) float smem[];
    float* sims_base = smem + YS_FLOATS;            // 4 buffers [32][136]

    const unsigned int smem_u32 = (unsigned int)__cvta_generic_to_shared(smem);
    const unsigned int mbar_u32 = smem_u32 + YS_BYTES + SIMS_TOT * 4;

    const int tid  = threadIdx.x;
    const int b    = blockIdx.y;
    const int t0   = blockIdx.x * TT_;

    // fc_w/fc_b prefetch into registers (LDGs overlap the whole band phase)
    float wreg[WPF_];
    #pragma unroll
    for (int u = 0; u < WPF_; u++) {
        const int i = tid + u * NTHREADS_;          // 0..13055, l = 0..101
        const int l = i >> 7;
        const int o = i & 127;
        wreg[u] = (l < LOOKUP_) ? fc_w[l * 128 + o] : fc_b[o];
    }

    const int gid   = tid / GTHREADS_;              // k-group 0..3 (128 bins each)
    const int tidg  = tid - gid * GTHREADS_;
    const int warpg = tidg >> 5;                    // 0..5
    const int lane  = tidg & 31;
    const int g     = lane >> 2;
    const int t     = lane & 3;
    const int kbase = gid * 128;                    // element offset (halfs)
    const int n0w   = warpg * 24;                   // 3 n8-tiles per warp

    const unsigned int ysg_u32 = smem_u32 + (unsigned int)(gid * 2 * TMA_BYTES);

    // per-lane ldmatrix row/base precompute (SW128; 16B units, 128B rows)
    const int ri = lane & 7;
    const int q  = lane >> 3;                       // 0..3
    const int rA = PAD_ + (q & 1) * 8 + ri;
    const unsigned offA = (unsigned)(rA * 128);
    const int xA = rA & 7, cA = q >> 1;
    const int rB4 = n0w + (q >> 1) * 8 + ri;
    const unsigned offB4 = (unsigned)(rB4 * 128);
    const int xB4 = rB4 & 7, cB4 = q & 1;
    const int rB2 = n0w + 16 + ri;
    const unsigned offB2 = (unsigned)(rB2 * 128);
    const int xB2 = rB2 & 7, cB2 = q & 1;

    if (tid < NGROUPS_) {
        asm volatile("mbarrier.init.shared.b64 [%0], 1;"
                     :: "r"(mbar_u32 + tid * 8) : "memory");
    }
    __syncthreads();

    // one mbar per group; both chunk TMAs feed it (single wait)
    if (tidg == 0) {
        const unsigned int mb = mbar_u32 + gid * 8;
        asm volatile("mbarrier.arrive.expect_tx.shared.b64 _, [%0], %1;"
                     :: "r"(mb), "r"(2 * TMA_BYTES) : "memory");
        #pragma unroll
        for (int c = 0; c < 2; c++) {
            asm volatile(
                "cp.async.bulk.tensor.3d.shared::cta.global.tile.mbarrier::complete_tx::bytes "
                "[%0], [%1, {%2, %3, %4}], [%5];"
                :: "r"(ysg_u32 + (unsigned int)(c * TMA_BYTES)),
                   "l"((const void*)&tmap),
                   "r"(kbase + c * KCH_), "r"(t0 - PAD_), "r"(b),
                   "r"(mb) : "memory");
        }
    }

    float acc[2][3][4] = {};

    mbar_wait(mbar_u32 + gid * 8, 0);

    #pragma unroll
    for (int c = 0; c < 2; c++) {
        const unsigned int Yb = ysg_u32 + (unsigned int)(c * TMA_BYTES);
        #pragma unroll
        for (int kk = 0; kk < 4; kk++) {
            unsigned a[8], bb[6];
            const unsigned uA  = (unsigned)(((2 * kk + cA)  ^ xA)  << 4);
            const unsigned uB4 = (unsigned)(((2 * kk + cB4) ^ xB4) << 4);
            const unsigned uB2 = (unsigned)(((2 * kk + cB2) ^ xB2) << 4);
            ldsm_x4(Yb + offA  + uA,        a[0], a[1], a[2], a[3]);
            ldsm_x4(Yb + offA  + uA + 2048, a[4], a[5], a[6], a[7]);   // +16 rows
            ldsm_x4(Yb + offB4 + uB4,       bb[0], bb[1], bb[2], bb[3]);
            ldsm_x2(Yb + offB2 + uB2,       bb[4], bb[5]);
            #pragma unroll
            for (int nj = 0; nj < 3; nj++) {
                mma_f16(acc[0][nj], a[0], a[1], a[2], a[3], bb[2 * nj], bb[2 * nj + 1]);
                mma_f16(acc[1][nj], a[4], a[5], a[6], a[7], bb[2 * nj], bb[2 * nj + 1]);
            }
        }
    }

    // ---- each group writes its OWN sims buffer (no RMW, no pair barrier) ----
    float* sbuf = sims_base + gid * TT_ * SIMS_LD;
    #pragma unroll
    for (int mi = 0; mi < 2; mi++)
        #pragma unroll
        for (int nj = 0; nj < 3; nj++) {
            const int col = n0w + nj * 8 + 2 * t;
            if (col < 132) {
                #pragma unroll
                for (int h = 0; h < 2; h++) {
                    const int row = mi * 16 + g + h * 8;
                    *(float2*)(sbuf + row * SIMS_LD + col) =
                        make_float2(acc[mi][nj][2 * h], acc[mi][nj][2 * h + 1]);
                }
            }
        }
    __syncthreads();

    // ---------------- epilogue: out = relu(win @ W + b), fp16 GEMM ----------
    __half* win_h = (__half*)smem;                       // [32][112]
    __half* Wsm_h = (__half*)smem + TT_ * WIN_K;         // [112][136]
    const float* s0 = sims_base;
    const float* s1 = sims_base + 1 * TT_ * SIMS_LD;
    const float* s2 = sims_base + 2 * TT_ * SIMS_LD;
    const float* s3 = sims_base + 3 * TT_ * SIMS_LD;

    for (int i = tid; i < TT_ * WIN_K; i += NTHREADS_) {
        const int c = i / WIN_K;
        const int l = i - c * WIN_K;
        float v = 0.f;
        if (l < LOOKUP_) {
            const int idx = c * SIMS_LD + c + l;
            v = (s0[idx] + s1[idx]) + (s2[idx] + s3[idx]);
        } else if (l == LOOKUP_) {
            v = 1.0f;                                    // bias row selector
        }
        win_h[i] = __float2half_rn(v);
    }
    #pragma unroll
    for (int u = 0; u < WPF_; u++) {
        const int i = tid + u * NTHREADS_;               // covers l = 0..101
        const int l = i >> 7;
        const int o = i & 127;
        Wsm_h[l * W_LDH + o] = __float2half_rn(wreg[u]);
    }
    for (int i = tid; i < 10 * 128; i += NTHREADS_) {    // zero rows 102..111
        const int l = 102 + (i >> 7);
        Wsm_h[l * W_LDH + (i & 127)] = __ushort_as_half((unsigned short)0);
    }
    __syncthreads();

    const int w = tid >> 5;
    if (w < 16) {
        const int m0e = (w & 1) * 16;
        const int n0e = (w >> 1) * 16;

        wmma::fragment<wmma::matrix_a, 16, 16, 16, __half, wmma::row_major> ea;
        wmma::fragment<wmma::matrix_b, 16, 16, 16, __half, wmma::row_major> eb;
        wmma::fragment<wmma::accumulator, 16, 16, 16, float> ec;
        wmma::fill_fragment(ec, 0.0f);

        #pragma unroll
        for (int kk = 0; kk < WIN_K / 16; kk++) {        // 7 k-steps
            wmma::load_matrix_sync(ea, win_h + m0e * WIN_K + kk * 16, WIN_K);
            wmma::load_matrix_sync(eb, Wsm_h + kk * 16 * W_LDH + n0e, W_LDH);
            wmma::mma_sync(ec, ea, eb, ec);
        }
        #pragma unroll
        for (int i = 0; i < ec.num_elements; i++)
            ec.x[i] = fmaxf(ec.x[i], 0.0f);

        float* op = out + ((size_t)b * T_ + t0 + m0e) * ODIM_ + n0e;
        wmma::store_matrix_sync(op, ec, ODIM_, wmma::mem_row_major);
    }
}

// ---------------------------------------------------------------------------
typedef CUresult (*EncodeTiledFn)(
    CUtensorMap*, CUtensorMapDataType, cuuint32_t, void*,
    const cuuint64_t*, const cuuint64_t*, const cuuint32_t*, const cuuint32_t*,
    CUtensorMapInterleave, CUtensorMapSwizzle, CUtensorMapL2promotion,
    CUtensorMapFloatOOBfill);

extern "C" void kernel_launch(void* const* d_in, const int* in_sizes, int n_in,
                              void* d_out, int out_size)
{
    const int*   frames = (const int*)d_in[0];
    const float* fc_w   = (const float*)d_in[1];
    const float* fc_b   = (const float*)d_in[2];
    float*       out    = (float*)d_out;

    void* hist_ptr = nullptr;
    cudaGetSymbolAddress(&hist_ptr, g_hist_h);

    EncodeTiledFn encode = nullptr;
    cudaDriverEntryPointQueryResult qr;
    cudaGetDriverEntryPoint("cuTensorMapEncodeTiled", (void**)&encode,
                            cudaEnableDefault, &qr);

    CUtensorMap tmap;
    cuuint64_t dims[3]    = {NBINS_, T_, B_};
    cuuint64_t strides[2] = {NBINS_ * 2ull, (cuuint64_t)T_ * NBINS_ * 2ull};
    cuuint32_t box[3]     = {KCH_, JT_, 1};
    cuuint32_t es[3]      = {1, 1, 1};
    encode(&tmap, CU_TENSOR_MAP_DATA_TYPE_FLOAT16, 3, hist_ptr,
           dims, strides, box, es,
           CU_TENSOR_MAP_INTERLEAVE_NONE, CU_TENSOR_MAP_SWIZZLE_128B,
           CU_TENSOR_MAP_L2_PROMOTION_L2_128B, CU_TENSOR_MAP_FLOAT_OOB_FILL_NONE);

    cudaFuncSetAttribute(band_fc_v8,
                         cudaFuncAttributeMaxDynamicSharedMemorySize, SMEM_BYTES);

    hist_kernel<<<B_ * T_, 256>>>(frames);

    dim3 grid(T_ / TT_, B_);
    band_fc_v8<<<grid, NTHREADS_, SMEM_BYTES>>>(tmap, fc_w, fc_b, out);
}